// round 8
// baseline (speedup 1.0000x reference)
#include <cuda_runtime.h>

#define T_TRIG 48
#define S_SPAN 128
#define NNODE  (T_TRIG * S_SPAN)     // 6144
#define DIM    128
#define NHEADS 4
#define HDIM   32

typedef unsigned long long ull;

__device__ float g_h   [NNODE * DIM];
__device__ float g_A   [NNODE * NHEADS];
__device__ float g_B   [NNODE * NHEADS];
__device__ float g_EA  [NNODE * NHEADS];
__device__ float g_EA5 [NNODE * NHEADS];
__device__ float g_EB  [NNODE * NHEADS];
__device__ float g_EB5 [NNODE * NHEADS];
__device__ float g_srow[NNODE * NHEADS];
__device__ float g_tmp [NNODE * DIM];
__device__ float g_x1  [NNODE * DIM];

// ---- packed f32x2 helpers -------------------------------------------------
__device__ __forceinline__ ull pk2(float x, float y) {
    ull r; asm("mov.b64 %0, {%1, %2};" : "=l"(r) : "f"(x), "f"(y)); return r;
}
__device__ __forceinline__ float2 upk2(ull v) {
    float2 r; asm("mov.b64 {%0, %1}, %2;" : "=f"(r.x), "=f"(r.y) : "l"(v)); return r;
}
__device__ __forceinline__ void fma2(ull& d, ull a, ull b) {
    asm("fma.rn.f32x2 %0, %1, %2, %0;" : "+l"(d) : "l"(a), "l"(b));
}

// ---------------------------------------------------------------------------
// K1: h = x @ W + attention dots + 4 exps per (node,head).
// Block = 128 threads, M=16, N=128, grid = 384.
// x staged in smem as DUPLICATED f32x2 pairs (xsd) -> inner loop has zero
// packing MOVs: per k4 = 12 LDS.128 + 32 fma2.
// W streamed via smem in 4 chunks of 32 k-rows, register-prefetched.
// ---------------------------------------------------------------------------
__global__ void __launch_bounds__(128)
k_gemm_attn(const float* __restrict__ x,
            const float* __restrict__ W,
            const float* __restrict__ att_src,
            const float* __restrict__ att_dst)
{
    __shared__ __align__(16) ull   xsd[16 * 128];  // 16 KB, (x,x) pairs
    __shared__ __align__(16) float Wb [32 * 128];  // 16 KB (one k-chunk)

    const int tid  = threadIdx.x;
    const int row0 = blockIdx.x * 16;

    // stage x (duplicated) and W chunk 0
#pragma unroll
    for (int i = 0; i < 4; i++) {
        const int idx = tid + 128 * i;           // float4 index 0..511
        const float4 v = ((const float4*)(x + row0 * 128))[idx];
        ull* p = &xsd[(idx >> 5) * 128 + (idx & 31) * 4];
        p[0] = pk2(v.x, v.x);
        p[1] = pk2(v.y, v.y);
        p[2] = pk2(v.z, v.z);
        p[3] = pk2(v.w, v.w);
    }
#pragma unroll
    for (int i = 0; i < 8; i++)
        ((float4*)Wb)[tid + 128 * i] = ((const float4*)W)[tid + 128 * i];
    __syncthreads();

    const int warp = tid >> 5;
    const int lane = tid & 31;
    const int mg   = lane >> 3;       // row group (4 rows)
    const int ng   = lane & 7;        // col group (4 cols)
    const int wcol = warp * 32 + ng * 4;

    ull acc2[4][2];
#pragma unroll
    for (int r = 0; r < 4; r++) { acc2[r][0] = 0ull; acc2[r][1] = 0ull; }

    for (int cc = 0; cc < 4; cc++) {
        float4 pre[8];
        if (cc < 3) {
#pragma unroll
            for (int i = 0; i < 8; i++)
                pre[i] = ((const float4*)W)[(cc + 1) * 1024 + tid + 128 * i];
        }

#pragma unroll
        for (int k4 = 0; k4 < 8; k4++) {
            ulonglong2 wv[4];
#pragma unroll
            for (int kk = 0; kk < 4; kk++)
                wv[kk] = *(const ulonglong2*)&Wb[(k4 * 4 + kk) * 128 + wcol];
#pragma unroll
            for (int r = 0; r < 4; r++) {
                const ull* xp = &xsd[(mg * 4 + r) * 128 + (cc * 8 + k4) * 4];
                const ulonglong2 x01 = *(const ulonglong2*)&xp[0];
                const ulonglong2 x23 = *(const ulonglong2*)&xp[2];
                fma2(acc2[r][0], x01.x, wv[0].x); fma2(acc2[r][1], x01.x, wv[0].y);
                fma2(acc2[r][0], x01.y, wv[1].x); fma2(acc2[r][1], x01.y, wv[1].y);
                fma2(acc2[r][0], x23.x, wv[2].x); fma2(acc2[r][1], x23.x, wv[2].y);
                fma2(acc2[r][0], x23.y, wv[3].x); fma2(acc2[r][1], x23.y, wv[3].y);
            }
        }

        if (cc < 3) {
            __syncthreads();
#pragma unroll
            for (int i = 0; i < 8; i++)
                ((float4*)Wb)[tid + 128 * i] = pre[i];
            __syncthreads();
        }
    }

    float acc[4][4];
#pragma unroll
    for (int r = 0; r < 4; r++) {
        const float2 lo = upk2(acc2[r][0]);
        const float2 hi = upk2(acc2[r][1]);
        acc[r][0] = lo.x; acc[r][1] = lo.y; acc[r][2] = hi.x; acc[r][3] = hi.y;
        *(float4*)&g_h[(row0 + mg * 4 + r) * 128 + wcol] =
            make_float4(lo.x, lo.y, hi.x, hi.y);
    }

    const float4 asv = *(const float4*)&att_src[warp * 32 + ng * 4];
    const float4 adv = *(const float4*)&att_dst[warp * 32 + ng * 4];

#pragma unroll
    for (int r = 0; r < 4; r++) {
        float ps = acc[r][0] * asv.x + acc[r][1] * asv.y + acc[r][2] * asv.z + acc[r][3] * asv.w;
        float pd = acc[r][0] * adv.x + acc[r][1] * adv.y + acc[r][2] * adv.z + acc[r][3] * adv.w;
#pragma unroll
        for (int o = 1; o < 8; o <<= 1) {
            ps += __shfl_xor_sync(0xffffffffu, ps, o);
            pd += __shfl_xor_sync(0xffffffffu, pd, o);
        }
        if (ng == 0) {
            const int n  = row0 + mg * 4 + r;
            const int i4 = n * 4 + warp;
            g_A  [i4] = ps;
            g_B  [i4] = pd;
            g_EA [i4] = __expf(ps);
            g_EA5[i4] = __expf(0.2f * ps);
            g_EB [i4] = __expf(pd);
            g_EB5[i4] = __expf(0.2f * pd);
        }
    }
}

// ---------------------------------------------------------------------------
// K2: row aggregation (unnormalized) + row part of softmax denominator.
// Block = (r, head, c-half). grid = 384, 128 threads.
// Weights staged DUPLICATED (wsd) -> per j: 3 LDS.128 + 8 fma2, no MOVs.
// ---------------------------------------------------------------------------
__global__ void __launch_bounds__(128)
k_row_agg()
{
    const int b  = blockIdx.x;
    const int r  = b >> 3;
    const int hh = (b >> 1) & 3;
    const int ch = b & 1;

    __shared__ __align__(16) float Hs[128 * 36];
    __shared__ __align__(16) ull   wsd[32 * 66];    // (w,w) pairs
    __shared__ float As[128], EAs[128], EA5s[128];
    __shared__ float Bs[64], EBs[64], EB5s[64];
    __shared__ float Ssum2[2][64];

    const int tid = threadIdx.x;

#pragma unroll
    for (int i = tid; i < 1024; i += 128) {
        const int cp = i >> 3, v = i & 7;
        *(float4*)&Hs[cp * 36 + v * 4] =
            *(const float4*)&g_h[(r * 128 + cp) * 128 + hh * 32 + v * 4];
    }
    {
        const int idx = (r * 128 + tid) * 4 + hh;
        As  [tid] = g_A  [idx];
        EAs [tid] = g_EA [idx];
        EA5s[tid] = g_EA5[idx];
    }
    if (tid < 64) {
        const int idx = (r * 128 + ch * 64 + tid) * 4 + hh;
        Bs  [tid] = g_B  [idx];
        EBs [tid] = g_EB [idx];
        EB5s[tid] = g_EB5[idx];
    }
    __syncthreads();

    const int d  = tid & 63;
    const int jh = tid >> 6;
    const float Bv   = Bs[d];
    const float EBv  = EBs[d];
    const float EB5v = EB5s[d];
    float srun = 0.f;

    const int dg = tid >> 3;
    const int qg = tid & 7;

    ull acc2[4][2];
#pragma unroll
    for (int a = 0; a < 4; a++) { acc2[a][0] = 0ull; acc2[a][1] = 0ull; }

    for (int cc = 0; cc < 4; cc++) {
#pragma unroll
        for (int jj = 0; jj < 16; jj++) {
            const int j  = jh * 16 + jj;
            const int jx = cc * 32 + j;
            const float xv = As[jx] + Bv;
            const float w = xv > 0.f ? EAs[jx] * EBv : EA5s[jx] * EB5v;
            wsd[j * 66 + d] = pk2(w, w);
            srun += w;
        }
        __syncthreads();

#pragma unroll
        for (int j = 0; j < 32; j++) {
            const ull* wp = &wsd[j * 66 + dg * 4];
            const ulonglong2 w01 = *(const ulonglong2*)&wp[0];
            const ulonglong2 w23 = *(const ulonglong2*)&wp[2];
            const ulonglong2 hv = *(const ulonglong2*)&Hs[(cc * 32 + j) * 36 + qg * 4];
            fma2(acc2[0][0], w01.x, hv.x); fma2(acc2[0][1], w01.x, hv.y);
            fma2(acc2[1][0], w01.y, hv.x); fma2(acc2[1][1], w01.y, hv.y);
            fma2(acc2[2][0], w23.x, hv.x); fma2(acc2[2][1], w23.x, hv.y);
            fma2(acc2[3][0], w23.y, hv.x); fma2(acc2[3][1], w23.y, hv.y);
        }
        __syncthreads();
    }

#pragma unroll
    for (int a = 0; a < 4; a++) {
        const int dst = ch * 64 + dg * 4 + a;
        const float2 lo = upk2(acc2[a][0]);
        const float2 hi = upk2(acc2[a][1]);
        *(float4*)&g_tmp[(r * 128 + dst) * 128 + hh * 32 + qg * 4] =
            make_float4(lo.x, lo.y, hi.x, hi.y);
    }

    Ssum2[jh][d] = srun;
    __syncthreads();
    if (tid < 64)
        g_srow[(r * 128 + ch * 64 + tid) * 4 + hh] = Ssum2[0][tid] + Ssum2[1][tid];
}

// ---------------------------------------------------------------------------
// K3: column aggregation + denominator finalize + normalize + bias + ELU.
// Block per column c: grid = 128, 384 threads. Weights duplicated in smem,
// 6 chunks of 8 t-rows (static smem cap).
// ---------------------------------------------------------------------------
__global__ void __launch_bounds__(384)
k_col_agg(const float* __restrict__ bias, float* __restrict__ out)
{
    const int c   = blockIdx.x;
    const int tid = threadIdx.x;

    __shared__ __align__(16) float Hs[48 * 136];
    __shared__ __align__(16) ull   wsd[8 * 224];   // [tl][h*56 + rr], (w,w)
    __shared__ float Acol[192], EAc[192], EA5c[192];
    __shared__ float Brc[192], EBrc[192], EB5rc[192];
    __shared__ float Srow[192], Rd[192];
    __shared__ float Sc2[2][192];
    __shared__ float bsh[128];

#pragma unroll
    for (int i = tid; i < 1536; i += 384) {
        const int t = i >> 5, v = i & 31;
        *(float4*)&Hs[t * 136 + v * 4] =
            *(const float4*)&g_h[(t * 128 + c) * 128 + v * 4];
    }
    if (tid < 192) {
        const int t = tid >> 2, h = tid & 3;
        const int idx = (t * 128 + c) * 4 + h;
        Acol [tid] = g_A   [idx];
        EAc  [tid] = g_EA  [idx];
        EA5c [tid] = g_EA5 [idx];
        Brc  [tid] = g_B   [idx];
        EBrc [tid] = g_EB  [idx];
        EB5rc[tid] = g_EB5 [idx];
        Srow [tid] = g_srow[idx];
    } else if (tid < 320) {
        bsh[tid - 192] = bias[tid - 192];
    }
    __syncthreads();

    // staging map: k = tid % 192 -> (rr, h); half selects 4 of 8 t's per chunk
    const int k    = tid < 192 ? tid : tid - 192;
    const int half = tid < 192 ? 0 : 1;
    const int rr   = k >> 2;
    const int h    = k & 3;
    const float Bv   = Brc[k];
    const float EBv  = EBrc[k];
    const float EB5v = EB5rc[k];
    float scrun = 0.f;

    const int rg   = tid >> 5;
    const int head = (tid >> 3) & 3;
    const int qg   = tid & 7;

    ull acc2[4][2];
#pragma unroll
    for (int a = 0; a < 4; a++) { acc2[a][0] = 0ull; acc2[a][1] = 0ull; }

    for (int chunk = 0; chunk < 6; chunk++) {
        const int t0 = chunk * 8;
#pragma unroll
        for (int i = 0; i < 4; i++) {
            const int tl = half * 4 + i;
            const int t  = t0 + tl;
            const int sx = t * 4 + h;
            const float xv = Acol[sx] + Bv;
            float w = xv > 0.f ? EAc[sx] * EBv : EA5c[sx] * EB5v;
            if (t == rr) w = 0.f;
            wsd[tl * 224 + h * 56 + rr] = pk2(w, w);
            scrun += w;
        }
        __syncthreads();

#pragma unroll
        for (int tl = 0; tl < 8; tl++) {
            const ull* wp = &wsd[tl * 224 + head * 56 + rg * 4];
            const ulonglong2 w01 = *(const ulonglong2*)&wp[0];
            const ulonglong2 w23 = *(const ulonglong2*)&wp[2];
            const ulonglong2 hv =
                *(const ulonglong2*)&Hs[(t0 + tl) * 136 + head * 32 + qg * 4];
            fma2(acc2[0][0], w01.x, hv.x); fma2(acc2[0][1], w01.x, hv.y);
            fma2(acc2[1][0], w01.y, hv.x); fma2(acc2[1][1], w01.y, hv.y);
            fma2(acc2[2][0], w23.x, hv.x); fma2(acc2[2][1], w23.x, hv.y);
            fma2(acc2[3][0], w23.y, hv.x); fma2(acc2[3][1], w23.y, hv.y);
        }
        __syncthreads();
    }

    Sc2[half][k] = scrun;
    __syncthreads();
    if (tid < 192)
        Rd[tid] = 1.f / (Srow[tid] + Sc2[0][tid] + Sc2[1][tid]);
    __syncthreads();

    const int bb = head * 32 + qg * 4;
    const float4 bv = *(const float4*)&bsh[bb];
#pragma unroll
    for (int a = 0; a < 4; a++) {
        const int r = rg * 4 + a;
        const float rd = Rd[r * 4 + head];
        const int base = (r * 128 + c) * 128 + bb;
        const float4 tv = *(const float4*)&g_tmp[base];
        const float2 lo = upk2(acc2[a][0]);
        const float2 hi = upk2(acc2[a][1]);
        float v0 = (lo.x + tv.x) * rd + bv.x;
        float v1 = (lo.y + tv.y) * rd + bv.y;
        float v2 = (hi.x + tv.z) * rd + bv.z;
        float v3 = (hi.y + tv.w) * rd + bv.w;
        v0 = v0 > 0.f ? v0 : (__expf(v0) - 1.f);
        v1 = v1 > 0.f ? v1 : (__expf(v1) - 1.f);
        v2 = v2 > 0.f ? v2 : (__expf(v2) - 1.f);
        v3 = v3 > 0.f ? v3 : (__expf(v3) - 1.f);
        *(float4*)&out[base] = make_float4(v0, v1, v2, v3);
    }
}

// ---------------------------------------------------------------------------
static void run_layer(const float* x, const float* W, const float* asrc,
                      const float* adst, const float* bias, float* out)
{
    k_gemm_attn<<<NNODE / 16, 128>>>(x, W, asrc, adst);
    k_row_agg<<<T_TRIG * NHEADS * 2, 128>>>();
    k_col_agg<<<S_SPAN, 384>>>(bias, out);
}

extern "C" void kernel_launch(void* const* d_in, const int* in_sizes, int n_in,
                              void* d_out, int out_size)
{
    const float* x0  = (const float*)d_in[0];
    const float* W1  = (const float*)d_in[1];
    const float* as1 = (const float*)d_in[2];
    const float* ad1 = (const float*)d_in[3];
    const float* b1  = (const float*)d_in[4];
    const float* W2  = (const float*)d_in[5];
    const float* as2 = (const float*)d_in[6];
    const float* ad2 = (const float*)d_in[7];
    const float* b2  = (const float*)d_in[8];

    float* x1 = nullptr;
    cudaGetSymbolAddress((void**)&x1, g_x1);

    run_layer(x0, W1, as1, ad1, b1, x1);
    run_layer(x1, W2, as2, ad2, b2, (float*)d_out);
}

// round 9
// speedup vs baseline: 1.1260x; 1.1260x over previous
#include <cuda_runtime.h>

#define T_TRIG 48
#define S_SPAN 128
#define NNODE  (T_TRIG * S_SPAN)     // 6144
#define DIM    128
#define NHEADS 4
#define HDIM   32

typedef unsigned long long ull;

__device__ float g_h   [NNODE * DIM];
__device__ float g_A   [NNODE * NHEADS];
__device__ float g_B   [NNODE * NHEADS];
__device__ float g_EA  [NNODE * NHEADS];
__device__ float g_EA5 [NNODE * NHEADS];
__device__ float g_EB  [NNODE * NHEADS];
__device__ float g_EB5 [NNODE * NHEADS];
__device__ float g_srow[NNODE * NHEADS];
__device__ float g_tmp [NNODE * DIM];
__device__ float g_x1  [NNODE * DIM];

// ---- packed f32x2 helpers -------------------------------------------------
__device__ __forceinline__ ull pk2(float x, float y) {
    ull r; asm("mov.b64 %0, {%1, %2};" : "=l"(r) : "f"(x), "f"(y)); return r;
}
__device__ __forceinline__ float2 upk2(ull v) {
    float2 r; asm("mov.b64 {%0, %1}, %2;" : "=f"(r.x), "=f"(r.y) : "l"(v)); return r;
}
__device__ __forceinline__ void fma2(ull& d, ull a, ull b) {
    asm("fma.rn.f32x2 %0, %1, %2, %0;" : "+l"(d) : "l"(a), "l"(b));
}

// ---------------------------------------------------------------------------
// K1: h = x @ W + attention dots + 4 exps per (node,head).
// Block = 256 threads (8 warps), M=16, N=128, grid = 384.
// Warp w: rows (w>>2)*8..+7, cols (w&3)*32..+31 (head = w&3).
// Thread tile = 2 rows x 4 cols. W ping-pong staged in smem (2 x 32 k-rows),
// register-prefetched: inner loop has no global loads, one sync per chunk.
// ---------------------------------------------------------------------------
__global__ void __launch_bounds__(256)
k_gemm_attn(const float* __restrict__ x,
            const float* __restrict__ W,
            const float* __restrict__ att_src,
            const float* __restrict__ att_dst)
{
    __shared__ __align__(16) float xs[16 * 128];       // 8 KB
    __shared__ __align__(16) float Wb[2][32 * 128];    // 32 KB ping-pong

    const int tid  = threadIdx.x;
    const int row0 = blockIdx.x * 16;

    // stage x (512 float4) and W chunk 0 (1024 float4)
#pragma unroll
    for (int i = 0; i < 2; i++)
        ((float4*)xs)[tid + 256 * i] = ((const float4*)(x + row0 * 128))[tid + 256 * i];
#pragma unroll
    for (int i = 0; i < 4; i++)
        ((float4*)Wb[0])[tid + 256 * i] = ((const float4*)W)[tid + 256 * i];

    // prefetch chunk 1
    float4 pre[4];
#pragma unroll
    for (int i = 0; i < 4; i++)
        pre[i] = ((const float4*)W)[1024 + tid + 256 * i];
    __syncthreads();

    const int warp = tid >> 5;
    const int lane = tid & 31;
    const int mg   = lane >> 3;              // 0..3 -> 2 rows each
    const int ng   = lane & 7;               // 0..7 -> 4 cols each
    const int head = warp & 3;
    const int rowl = (warp >> 2) * 8 + mg * 2;
    const int wcol = head * 32 + ng * 4;

    ull acc2[2][2];
    acc2[0][0] = acc2[0][1] = acc2[1][0] = acc2[1][1] = 0ull;

    for (int cc = 0; cc < 4; cc++) {
        const float* cur = Wb[cc & 1];

        // store prefetched chunk cc+1 into the other buffer, prefetch cc+2
        if (cc < 3) {
#pragma unroll
            for (int i = 0; i < 4; i++)
                ((float4*)Wb[(cc + 1) & 1])[tid + 256 * i] = pre[i];
            if (cc < 2) {
#pragma unroll
                for (int i = 0; i < 4; i++)
                    pre[i] = ((const float4*)W)[(cc + 2) * 1024 + tid + 256 * i];
            }
        }

#pragma unroll
        for (int k4 = 0; k4 < 8; k4++) {
            ulonglong2 wv[4];
#pragma unroll
            for (int kk = 0; kk < 4; kk++)
                wv[kk] = *(const ulonglong2*)&cur[(k4 * 4 + kk) * 128 + wcol];
#pragma unroll
            for (int r = 0; r < 2; r++) {
                const float4 xv = *(const float4*)&xs[(rowl + r) * 128 + (cc * 8 + k4) * 4];
                ull xx;
                xx = pk2(xv.x, xv.x); fma2(acc2[r][0], xx, wv[0].x); fma2(acc2[r][1], xx, wv[0].y);
                xx = pk2(xv.y, xv.y); fma2(acc2[r][0], xx, wv[1].x); fma2(acc2[r][1], xx, wv[1].y);
                xx = pk2(xv.z, xv.z); fma2(acc2[r][0], xx, wv[2].x); fma2(acc2[r][1], xx, wv[2].y);
                xx = pk2(xv.w, xv.w); fma2(acc2[r][0], xx, wv[3].x); fma2(acc2[r][1], xx, wv[3].y);
            }
        }
        __syncthreads();   // next buffer's stores visible / cur free for rewrite
    }

    float acc[2][4];
#pragma unroll
    for (int r = 0; r < 2; r++) {
        const float2 lo = upk2(acc2[r][0]);
        const float2 hi = upk2(acc2[r][1]);
        acc[r][0] = lo.x; acc[r][1] = lo.y; acc[r][2] = hi.x; acc[r][3] = hi.y;
        *(float4*)&g_h[(row0 + rowl + r) * 128 + wcol] =
            make_float4(lo.x, lo.y, hi.x, hi.y);
    }

    const float4 asv = *(const float4*)&att_src[head * 32 + ng * 4];
    const float4 adv = *(const float4*)&att_dst[head * 32 + ng * 4];

#pragma unroll
    for (int r = 0; r < 2; r++) {
        float ps = acc[r][0] * asv.x + acc[r][1] * asv.y + acc[r][2] * asv.z + acc[r][3] * asv.w;
        float pd = acc[r][0] * adv.x + acc[r][1] * adv.y + acc[r][2] * adv.z + acc[r][3] * adv.w;
#pragma unroll
        for (int o = 1; o < 8; o <<= 1) {
            ps += __shfl_xor_sync(0xffffffffu, ps, o);
            pd += __shfl_xor_sync(0xffffffffu, pd, o);
        }
        if (ng == 0) {
            const int n  = row0 + rowl + r;
            const int i4 = n * 4 + head;
            g_A  [i4] = ps;
            g_B  [i4] = pd;
            g_EA [i4] = __expf(ps);
            g_EA5[i4] = __expf(0.2f * ps);
            g_EB [i4] = __expf(pd);
            g_EB5[i4] = __expf(0.2f * pd);
        }
    }
}

// ---------------------------------------------------------------------------
// K2: row aggregation (unnormalized) + row part of softmax denominator.
// Block = (r, head, c-half). grid = 384, 128 threads, f32x2 inner loop.
// ---------------------------------------------------------------------------
__global__ void __launch_bounds__(128)
k_row_agg()
{
    const int b  = blockIdx.x;
    const int r  = b >> 3;
    const int hh = (b >> 1) & 3;
    const int ch = b & 1;

    __shared__ __align__(16) float Hs[128 * 36];
    __shared__ __align__(16) float ws[32 * 68];
    __shared__ float As[128], EAs[128], EA5s[128];
    __shared__ float Bs[64], EBs[64], EB5s[64];
    __shared__ float Ssum2[2][64];

    const int tid = threadIdx.x;

#pragma unroll
    for (int i = tid; i < 1024; i += 128) {
        const int cp = i >> 3, v = i & 7;
        *(float4*)&Hs[cp * 36 + v * 4] =
            *(const float4*)&g_h[(r * 128 + cp) * 128 + hh * 32 + v * 4];
    }
    {
        const int idx = (r * 128 + tid) * 4 + hh;
        As  [tid] = g_A  [idx];
        EAs [tid] = g_EA [idx];
        EA5s[tid] = g_EA5[idx];
    }
    if (tid < 64) {
        const int idx = (r * 128 + ch * 64 + tid) * 4 + hh;
        Bs  [tid] = g_B  [idx];
        EBs [tid] = g_EB [idx];
        EB5s[tid] = g_EB5[idx];
    }
    __syncthreads();

    const int d  = tid & 63;
    const int jh = tid >> 6;
    const float Bv   = Bs[d];
    const float EBv  = EBs[d];
    const float EB5v = EB5s[d];
    float srun = 0.f;

    const int dg = tid >> 3;
    const int qg = tid & 7;

    ull acc2[4][2];
#pragma unroll
    for (int a = 0; a < 4; a++) { acc2[a][0] = 0ull; acc2[a][1] = 0ull; }

    for (int cc = 0; cc < 4; cc++) {
#pragma unroll
        for (int jj = 0; jj < 16; jj++) {
            const int j  = jh * 16 + jj;
            const int jx = cc * 32 + j;
            const float xv = As[jx] + Bv;
            const float w = xv > 0.f ? EAs[jx] * EBv : EA5s[jx] * EB5v;
            ws[j * 68 + d] = w;
            srun += w;
        }
        __syncthreads();

#pragma unroll
        for (int j = 0; j < 32; j++) {
            const float4 wv = *(const float4*)&ws[j * 68 + dg * 4];
            const ulonglong2 hv = *(const ulonglong2*)&Hs[(cc * 32 + j) * 36 + qg * 4];
            ull ww;
            ww = pk2(wv.x, wv.x); fma2(acc2[0][0], ww, hv.x); fma2(acc2[0][1], ww, hv.y);
            ww = pk2(wv.y, wv.y); fma2(acc2[1][0], ww, hv.x); fma2(acc2[1][1], ww, hv.y);
            ww = pk2(wv.z, wv.z); fma2(acc2[2][0], ww, hv.x); fma2(acc2[2][1], ww, hv.y);
            ww = pk2(wv.w, wv.w); fma2(acc2[3][0], ww, hv.x); fma2(acc2[3][1], ww, hv.y);
        }
        __syncthreads();
    }

#pragma unroll
    for (int a = 0; a < 4; a++) {
        const int dst = ch * 64 + dg * 4 + a;
        const float2 lo = upk2(acc2[a][0]);
        const float2 hi = upk2(acc2[a][1]);
        *(float4*)&g_tmp[(r * 128 + dst) * 128 + hh * 32 + qg * 4] =
            make_float4(lo.x, lo.y, hi.x, hi.y);
    }

    Ssum2[jh][d] = srun;
    __syncthreads();
    if (tid < 64)
        g_srow[(r * 128 + ch * 64 + tid) * 4 + hh] = Ssum2[0][tid] + Ssum2[1][tid];
}

// ---------------------------------------------------------------------------
// K3: column aggregation + denominator finalize + normalize + bias + ELU.
// Block per column c: grid = 128, 384 threads, f32x2 inner loop.
// ---------------------------------------------------------------------------
__global__ void __launch_bounds__(384)
k_col_agg(const float* __restrict__ bias, float* __restrict__ out)
{
    const int c   = blockIdx.x;
    const int tid = threadIdx.x;

    __shared__ __align__(16) float Hs[48 * 136];
    __shared__ __align__(16) float ws[16 * 224];
    __shared__ float Acol[192], EAc[192], EA5c[192];
    __shared__ float Brc[192], EBrc[192], EB5rc[192];
    __shared__ float Srow[192], Rd[192];
    __shared__ float Sc2[2][192];
    __shared__ float bsh[128];

#pragma unroll
    for (int i = tid; i < 1536; i += 384) {
        const int t = i >> 5, v = i & 31;
        *(float4*)&Hs[t * 136 + v * 4] =
            *(const float4*)&g_h[(t * 128 + c) * 128 + v * 4];
    }
    if (tid < 192) {
        const int t = tid >> 2, h = tid & 3;
        const int idx = (t * 128 + c) * 4 + h;
        Acol [tid] = g_A   [idx];
        EAc  [tid] = g_EA  [idx];
        EA5c [tid] = g_EA5 [idx];
        Brc  [tid] = g_B   [idx];
        EBrc [tid] = g_EB  [idx];
        EB5rc[tid] = g_EB5 [idx];
        Srow [tid] = g_srow[idx];
    } else if (tid < 320) {
        bsh[tid - 192] = bias[tid - 192];
    }
    __syncthreads();

    const int k    = tid < 192 ? tid : tid - 192;
    const int half = tid < 192 ? 0 : 1;
    const int rr   = k >> 2;
    const int h    = k & 3;
    const float Bv   = Brc[k];
    const float EBv  = EBrc[k];
    const float EB5v = EB5rc[k];
    float scrun = 0.f;

    const int rg   = tid >> 5;
    const int head = (tid >> 3) & 3;
    const int qg   = tid & 7;

    ull acc2[4][2];
#pragma unroll
    for (int a = 0; a < 4; a++) { acc2[a][0] = 0ull; acc2[a][1] = 0ull; }

    for (int chunk = 0; chunk < 3; chunk++) {
        const int t0 = chunk * 16;
#pragma unroll
        for (int i = 0; i < 8; i++) {
            const int tl = half * 8 + i;
            const int t  = t0 + tl;
            const int sx = t * 4 + h;
            const float xv = Acol[sx] + Bv;
            float w = xv > 0.f ? EAc[sx] * EBv : EA5c[sx] * EB5v;
            if (t == rr) w = 0.f;
            ws[tl * 224 + h * 56 + rr] = w;
            scrun += w;
        }
        __syncthreads();

#pragma unroll
        for (int tl = 0; tl < 16; tl++) {
            const float4 wv = *(const float4*)&ws[tl * 224 + head * 56 + rg * 4];
            const ulonglong2 hv =
                *(const ulonglong2*)&Hs[(t0 + tl) * 136 + head * 32 + qg * 4];
            ull ww;
            ww = pk2(wv.x, wv.x); fma2(acc2[0][0], ww, hv.x); fma2(acc2[0][1], ww, hv.y);
            ww = pk2(wv.y, wv.y); fma2(acc2[1][0], ww, hv.x); fma2(acc2[1][1], ww, hv.y);
            ww = pk2(wv.z, wv.z); fma2(acc2[2][0], ww, hv.x); fma2(acc2[2][1], ww, hv.y);
            ww = pk2(wv.w, wv.w); fma2(acc2[3][0], ww, hv.x); fma2(acc2[3][1], ww, hv.y);
        }
        __syncthreads();
    }

    Sc2[half][k] = scrun;
    __syncthreads();
    if (tid < 192)
        Rd[tid] = 1.f / (Srow[tid] + Sc2[0][tid] + Sc2[1][tid]);
    __syncthreads();

    const int bb = head * 32 + qg * 4;
    const float4 bv = *(const float4*)&bsh[bb];
#pragma unroll
    for (int a = 0; a < 4; a++) {
        const int r = rg * 4 + a;
        const float rd = Rd[r * 4 + head];
        const int base = (r * 128 + c) * 128 + bb;
        const float4 tv = *(const float4*)&g_tmp[base];
        const float2 lo = upk2(acc2[a][0]);
        const float2 hi = upk2(acc2[a][1]);
        float v0 = (lo.x + tv.x) * rd + bv.x;
        float v1 = (lo.y + tv.y) * rd + bv.y;
        float v2 = (hi.x + tv.z) * rd + bv.z;
        float v3 = (hi.y + tv.w) * rd + bv.w;
        v0 = v0 > 0.f ? v0 : (__expf(v0) - 1.f);
        v1 = v1 > 0.f ? v1 : (__expf(v1) - 1.f);
        v2 = v2 > 0.f ? v2 : (__expf(v2) - 1.f);
        v3 = v3 > 0.f ? v3 : (__expf(v3) - 1.f);
        *(float4*)&out[base] = make_float4(v0, v1, v2, v3);
    }
}

// ---------------------------------------------------------------------------
static void run_layer(const float* x, const float* W, const float* asrc,
                      const float* adst, const float* bias, float* out)
{
    k_gemm_attn<<<NNODE / 16, 256>>>(x, W, asrc, adst);
    k_row_agg<<<T_TRIG * NHEADS * 2, 128>>>();
    k_col_agg<<<S_SPAN, 384>>>(bias, out);
}

extern "C" void kernel_launch(void* const* d_in, const int* in_sizes, int n_in,
                              void* d_out, int out_size)
{
    const float* x0  = (const float*)d_in[0];
    const float* W1  = (const float*)d_in[1];
    const float* as1 = (const float*)d_in[2];
    const float* ad1 = (const float*)d_in[3];
    const float* b1  = (const float*)d_in[4];
    const float* W2  = (const float*)d_in[5];
    const float* as2 = (const float*)d_in[6];
    const float* ad2 = (const float*)d_in[7];
    const float* b2  = (const float*)d_in[8];

    float* x1 = nullptr;
    cudaGetSymbolAddress((void**)&x1, g_x1);

    run_layer(x0, W1, as1, ad1, b1, x1);
    run_layer(x1, W2, as2, ad2, b2, (float*)d_out);
}

// round 10
// speedup vs baseline: 1.2776x; 1.1346x over previous
#include <cuda_runtime.h>

#define T_TRIG 48
#define S_SPAN 128
#define NNODE  (T_TRIG * S_SPAN)     // 6144
#define DIM    128
#define NHEADS 4
#define HDIM   32

typedef unsigned long long ull;
typedef unsigned int uint;

__device__ float g_h   [NNODE * DIM];
__device__ float g_A   [NNODE * NHEADS];
__device__ float g_B   [NNODE * NHEADS];
__device__ float g_EA  [NNODE * NHEADS];
__device__ float g_EA5 [NNODE * NHEADS];
__device__ float g_EB  [NNODE * NHEADS];
__device__ float g_EB5 [NNODE * NHEADS];
__device__ float g_srow[NNODE * NHEADS];
__device__ float g_tmp [NNODE * DIM];
__device__ float g_x1  [NNODE * DIM];
// fragment-ordered W (hi/lo tf32): [layer][(ks*16 + nt)*32 + lane]
__device__ float4 g_Wf [2 * 16 * 16 * 32];

// ---- packed f32x2 helpers (agg kernels) ------------------------------------
__device__ __forceinline__ ull pk2(float x, float y) {
    ull r; asm("mov.b64 %0, {%1, %2};" : "=l"(r) : "f"(x), "f"(y)); return r;
}
__device__ __forceinline__ float2 upk2(ull v) {
    float2 r; asm("mov.b64 {%0, %1}, %2;" : "=f"(r.x), "=f"(r.y) : "l"(v)); return r;
}
__device__ __forceinline__ void fma2(ull& d, ull a, ull b) {
    asm("fma.rn.f32x2 %0, %1, %2, %0;" : "+l"(d) : "l"(a), "l"(b));
}

// ---- tf32 helpers -----------------------------------------------------------
__device__ __forceinline__ uint cvt_tf32(float f) {
    uint r; asm("cvt.rna.tf32.f32 %0, %1;" : "=r"(r) : "f"(f)); return r;
}
__device__ __forceinline__ void mma_tf32(float& d0, float& d1, float& d2, float& d3,
                                         uint a0, uint a1, uint a2, uint a3,
                                         uint b0, uint b1) {
    asm("mma.sync.aligned.m16n8k8.row.col.f32.tf32.tf32.f32 "
        "{%0,%1,%2,%3}, {%4,%5,%6,%7}, {%8,%9}, {%0,%1,%2,%3};"
        : "+f"(d0), "+f"(d1), "+f"(d2), "+f"(d3)
        : "r"(a0), "r"(a1), "r"(a2), "r"(a3), "r"(b0), "r"(b1));
}

// ---------------------------------------------------------------------------
// K0: pack W1/W2 into fragment order with tf32 hi/lo split.
// Entry e = (ks, nt, lane): b0 = W[ks*8 + (lane&3)][nt*8 + (lane>>2)],
// b1 = same +4 k-rows. grid = 64 x 256 (one entry per thread).
// ---------------------------------------------------------------------------
__global__ void __launch_bounds__(256)
k_prep(const float* __restrict__ W1, const float* __restrict__ W2)
{
    const int gid   = blockIdx.x * 256 + threadIdx.x;   // 0..16383
    const int layer = gid >> 13;
    const int e     = gid & 8191;
    const int lane  = e & 31;
    const int nt    = (e >> 5) & 15;
    const int ks    = e >> 9;

    const float* W = layer ? W2 : W1;
    const int k0 = ks * 8 + (lane & 3);
    const int n  = nt * 8 + (lane >> 2);

    const float b0 = W[k0 * 128 + n];
    const float b1 = W[(k0 + 4) * 128 + n];
    const uint b0h = cvt_tf32(b0);
    const uint b1h = cvt_tf32(b1);
    const uint b0l = cvt_tf32(b0 - __uint_as_float(b0h));
    const uint b1l = cvt_tf32(b1 - __uint_as_float(b1h));

    g_Wf[layer * 8192 + e] = make_float4(__uint_as_float(b0h), __uint_as_float(b1h),
                                         __uint_as_float(b0l), __uint_as_float(b1l));
}

// ---------------------------------------------------------------------------
// K1: h = x @ W via tensor cores (3xTF32) + attention dots + 4 exps.
// Block = 128 thr (4 warps), M=16, grid = 384. Warp w covers head w
// (cols w*32..+31) as 4 n-tiles of 8. x in smem padded to 132 floats/row
// (bank-conflict-free A fragments). W fragments via coalesced LDG.128.
// ---------------------------------------------------------------------------
__global__ void __launch_bounds__(128)
k_gemm_attn(const float* __restrict__ x,
            const float4* __restrict__ Wf,
            const float* __restrict__ att_src,
            const float* __restrict__ att_dst)
{
    __shared__ __align__(16) float xs[16 * 132];

    const int tid  = threadIdx.x;
    const int row0 = blockIdx.x * 16;

    // stage x: 512 float4, padded rows
#pragma unroll
    for (int i = 0; i < 4; i++) {
        const int idx = tid + 128 * i;        // float4 index
        const int row = idx >> 5, c4 = idx & 31;
        *(float4*)&xs[row * 132 + c4 * 4] =
            ((const float4*)(x + row0 * 128))[idx];
    }
    __syncthreads();

    const int warp = tid >> 5;     // head / n-quarter
    const int lane = tid & 31;
    const int gid  = lane >> 2;    // 0..7
    const int tig  = lane & 3;     // 0..3

    float d[4][4];
#pragma unroll
    for (int nt = 0; nt < 4; nt++)
#pragma unroll
        for (int i = 0; i < 4; i++) d[nt][i] = 0.f;

#pragma unroll 4
    for (int ks = 0; ks < 16; ks++) {
        // A fragments (rows gid, gid+8; cols ks*8+tig, +4)
        const float a0f = xs[gid * 132 + ks * 8 + tig];
        const float a1f = xs[(gid + 8) * 132 + ks * 8 + tig];
        const float a2f = xs[gid * 132 + ks * 8 + tig + 4];
        const float a3f = xs[(gid + 8) * 132 + ks * 8 + tig + 4];
        const uint ah0 = cvt_tf32(a0f), ah1 = cvt_tf32(a1f);
        const uint ah2 = cvt_tf32(a2f), ah3 = cvt_tf32(a3f);
        const uint al0 = cvt_tf32(a0f - __uint_as_float(ah0));
        const uint al1 = cvt_tf32(a1f - __uint_as_float(ah1));
        const uint al2 = cvt_tf32(a2f - __uint_as_float(ah2));
        const uint al3 = cvt_tf32(a3f - __uint_as_float(ah3));

#pragma unroll
        for (int nt = 0; nt < 4; nt++) {
            const float4 bf = __ldg(&Wf[(ks * 16 + warp * 4 + nt) * 32 + lane]);
            const uint bh0 = __float_as_uint(bf.x);
            const uint bh1 = __float_as_uint(bf.y);
            const uint bl0 = __float_as_uint(bf.z);
            const uint bl1 = __float_as_uint(bf.w);
            mma_tf32(d[nt][0], d[nt][1], d[nt][2], d[nt][3],
                     ah0, ah1, ah2, ah3, bh0, bh1);
            mma_tf32(d[nt][0], d[nt][1], d[nt][2], d[nt][3],
                     ah0, ah1, ah2, ah3, bl0, bl1);
            mma_tf32(d[nt][0], d[nt][1], d[nt][2], d[nt][3],
                     al0, al1, al2, al3, bh0, bh1);
        }
    }

    // store h and compute attention dots; head == warp
    float psr0 = 0.f, psr8 = 0.f, pdr0 = 0.f, pdr8 = 0.f;
#pragma unroll
    for (int nt = 0; nt < 4; nt++) {
        const int col = warp * 32 + nt * 8 + 2 * tig;
        *(float2*)&g_h[(row0 + gid) * 128 + col]     = make_float2(d[nt][0], d[nt][1]);
        *(float2*)&g_h[(row0 + gid + 8) * 128 + col] = make_float2(d[nt][2], d[nt][3]);

        const float2 as = *(const float2*)&att_src[col];
        const float2 ad = *(const float2*)&att_dst[col];
        psr0 += d[nt][0] * as.x + d[nt][1] * as.y;
        psr8 += d[nt][2] * as.x + d[nt][3] * as.y;
        pdr0 += d[nt][0] * ad.x + d[nt][1] * ad.y;
        pdr8 += d[nt][2] * ad.x + d[nt][3] * ad.y;
    }
    // reduce over tig (lanes gid*4 + tig)
#pragma unroll
    for (int o = 1; o < 4; o <<= 1) {
        psr0 += __shfl_xor_sync(0xffffffffu, psr0, o);
        psr8 += __shfl_xor_sync(0xffffffffu, psr8, o);
        pdr0 += __shfl_xor_sync(0xffffffffu, pdr0, o);
        pdr8 += __shfl_xor_sync(0xffffffffu, pdr8, o);
    }
    if (tig == 0) {
        const int n0 = row0 + gid;
        const int n8 = row0 + gid + 8;
        int i4 = n0 * 4 + warp;
        g_A[i4] = psr0;  g_B[i4] = pdr0;
        g_EA[i4]  = __expf(psr0);        g_EB[i4]  = __expf(pdr0);
        g_EA5[i4] = __expf(0.2f * psr0); g_EB5[i4] = __expf(0.2f * pdr0);
        i4 = n8 * 4 + warp;
        g_A[i4] = psr8;  g_B[i4] = pdr8;
        g_EA[i4]  = __expf(psr8);        g_EB[i4]  = __expf(pdr8);
        g_EA5[i4] = __expf(0.2f * psr8); g_EB5[i4] = __expf(0.2f * pdr8);
    }
}

// ---------------------------------------------------------------------------
// K2: row aggregation (unnormalized) + row part of softmax denominator.
// Block = (r, head, c-half). grid = 384, 128 threads, f32x2 inner loop.
// ---------------------------------------------------------------------------
__global__ void __launch_bounds__(128)
k_row_agg()
{
    const int b  = blockIdx.x;
    const int r  = b >> 3;
    const int hh = (b >> 1) & 3;
    const int ch = b & 1;

    __shared__ __align__(16) float Hs[128 * 36];
    __shared__ __align__(16) float ws[32 * 68];
    __shared__ float As[128], EAs[128], EA5s[128];
    __shared__ float Bs[64], EBs[64], EB5s[64];
    __shared__ float Ssum2[2][64];

    const int tid = threadIdx.x;

#pragma unroll
    for (int i = tid; i < 1024; i += 128) {
        const int cp = i >> 3, v = i & 7;
        *(float4*)&Hs[cp * 36 + v * 4] =
            *(const float4*)&g_h[(r * 128 + cp) * 128 + hh * 32 + v * 4];
    }
    {
        const int idx = (r * 128 + tid) * 4 + hh;
        As  [tid] = g_A  [idx];
        EAs [tid] = g_EA [idx];
        EA5s[tid] = g_EA5[idx];
    }
    if (tid < 64) {
        const int idx = (r * 128 + ch * 64 + tid) * 4 + hh;
        Bs  [tid] = g_B  [idx];
        EBs [tid] = g_EB [idx];
        EB5s[tid] = g_EB5[idx];
    }
    __syncthreads();

    const int d  = tid & 63;
    const int jh = tid >> 6;
    const float Bv   = Bs[d];
    const float EBv  = EBs[d];
    const float EB5v = EB5s[d];
    float srun = 0.f;

    const int dg = tid >> 3;
    const int qg = tid & 7;

    ull acc2[4][2];
#pragma unroll
    for (int a = 0; a < 4; a++) { acc2[a][0] = 0ull; acc2[a][1] = 0ull; }

    for (int cc = 0; cc < 4; cc++) {
#pragma unroll
        for (int jj = 0; jj < 16; jj++) {
            const int j  = jh * 16 + jj;
            const int jx = cc * 32 + j;
            const float xv = As[jx] + Bv;
            const float w = xv > 0.f ? EAs[jx] * EBv : EA5s[jx] * EB5v;
            ws[j * 68 + d] = w;
            srun += w;
        }
        __syncthreads();

#pragma unroll
        for (int j = 0; j < 32; j++) {
            const float4 wv = *(const float4*)&ws[j * 68 + dg * 4];
            const ulonglong2 hv = *(const ulonglong2*)&Hs[(cc * 32 + j) * 36 + qg * 4];
            ull ww;
            ww = pk2(wv.x, wv.x); fma2(acc2[0][0], ww, hv.x); fma2(acc2[0][1], ww, hv.y);
            ww = pk2(wv.y, wv.y); fma2(acc2[1][0], ww, hv.x); fma2(acc2[1][1], ww, hv.y);
            ww = pk2(wv.z, wv.z); fma2(acc2[2][0], ww, hv.x); fma2(acc2[2][1], ww, hv.y);
            ww = pk2(wv.w, wv.w); fma2(acc2[3][0], ww, hv.x); fma2(acc2[3][1], ww, hv.y);
        }
        __syncthreads();
    }

#pragma unroll
    for (int a = 0; a < 4; a++) {
        const int dst = ch * 64 + dg * 4 + a;
        const float2 lo = upk2(acc2[a][0]);
        const float2 hi = upk2(acc2[a][1]);
        *(float4*)&g_tmp[(r * 128 + dst) * 128 + hh * 32 + qg * 4] =
            make_float4(lo.x, lo.y, hi.x, hi.y);
    }

    Ssum2[jh][d] = srun;
    __syncthreads();
    if (tid < 64)
        g_srow[(r * 128 + ch * 64 + tid) * 4 + hh] = Ssum2[0][tid] + Ssum2[1][tid];
}

// ---------------------------------------------------------------------------
// K3: column aggregation + denominator finalize + normalize + bias + ELU.
// Block per column c: grid = 128, 384 threads, f32x2 inner loop.
// ---------------------------------------------------------------------------
__global__ void __launch_bounds__(384)
k_col_agg(const float* __restrict__ bias, float* __restrict__ out)
{
    const int c   = blockIdx.x;
    const int tid = threadIdx.x;

    __shared__ __align__(16) float Hs[48 * 136];
    __shared__ __align__(16) float ws[16 * 224];
    __shared__ float Acol[192], EAc[192], EA5c[192];
    __shared__ float Brc[192], EBrc[192], EB5rc[192];
    __shared__ float Srow[192], Rd[192];
    __shared__ float Sc2[2][192];
    __shared__ float bsh[128];

#pragma unroll
    for (int i = tid; i < 1536; i += 384) {
        const int t = i >> 5, v = i & 31;
        *(float4*)&Hs[t * 136 + v * 4] =
            *(const float4*)&g_h[(t * 128 + c) * 128 + v * 4];
    }
    if (tid < 192) {
        const int t = tid >> 2, h = tid & 3;
        const int idx = (t * 128 + c) * 4 + h;
        Acol [tid] = g_A   [idx];
        EAc  [tid] = g_EA  [idx];
        EA5c [tid] = g_EA5 [idx];
        Brc  [tid] = g_B   [idx];
        EBrc [tid] = g_EB  [idx];
        EB5rc[tid] = g_EB5 [idx];
        Srow [tid] = g_srow[idx];
    } else if (tid < 320) {
        bsh[tid - 192] = bias[tid - 192];
    }
    __syncthreads();

    const int k    = tid < 192 ? tid : tid - 192;
    const int half = tid < 192 ? 0 : 1;
    const int rr   = k >> 2;
    const int h    = k & 3;
    const float Bv   = Brc[k];
    const float EBv  = EBrc[k];
    const float EB5v = EB5rc[k];
    float scrun = 0.f;

    const int rg   = tid >> 5;
    const int head = (tid >> 3) & 3;
    const int qg   = tid & 7;

    ull acc2[4][2];
#pragma unroll
    for (int a = 0; a < 4; a++) { acc2[a][0] = 0ull; acc2[a][1] = 0ull; }

    for (int chunk = 0; chunk < 3; chunk++) {
        const int t0 = chunk * 16;
#pragma unroll
        for (int i = 0; i < 8; i++) {
            const int tl = half * 8 + i;
            const int t  = t0 + tl;
            const int sx = t * 4 + h;
            const float xv = Acol[sx] + Bv;
            float w = xv > 0.f ? EAc[sx] * EBv : EA5c[sx] * EB5v;
            if (t == rr) w = 0.f;
            ws[tl * 224 + h * 56 + rr] = w;
            scrun += w;
        }
        __syncthreads();

#pragma unroll
        for (int tl = 0; tl < 16; tl++) {
            const float4 wv = *(const float4*)&ws[tl * 224 + head * 56 + rg * 4];
            const ulonglong2 hv =
                *(const ulonglong2*)&Hs[(t0 + tl) * 136 + head * 32 + qg * 4];
            ull ww;
            ww = pk2(wv.x, wv.x); fma2(acc2[0][0], ww, hv.x); fma2(acc2[0][1], ww, hv.y);
            ww = pk2(wv.y, wv.y); fma2(acc2[1][0], ww, hv.x); fma2(acc2[1][1], ww, hv.y);
            ww = pk2(wv.z, wv.z); fma2(acc2[2][0], ww, hv.x); fma2(acc2[2][1], ww, hv.y);
            ww = pk2(wv.w, wv.w); fma2(acc2[3][0], ww, hv.x); fma2(acc2[3][1], ww, hv.y);
        }
        __syncthreads();
    }

    Sc2[half][k] = scrun;
    __syncthreads();
    if (tid < 192)
        Rd[tid] = 1.f / (Srow[tid] + Sc2[0][tid] + Sc2[1][tid]);
    __syncthreads();

    const int bb = head * 32 + qg * 4;
    const float4 bv = *(const float4*)&bsh[bb];
#pragma unroll
    for (int a = 0; a < 4; a++) {
        const int r = rg * 4 + a;
        const float rd = Rd[r * 4 + head];
        const int base = (r * 128 + c) * 128 + bb;
        const float4 tv = *(const float4*)&g_tmp[base];
        const float2 lo = upk2(acc2[a][0]);
        const float2 hi = upk2(acc2[a][1]);
        float v0 = (lo.x + tv.x) * rd + bv.x;
        float v1 = (lo.y + tv.y) * rd + bv.y;
        float v2 = (hi.x + tv.z) * rd + bv.z;
        float v3 = (hi.y + tv.w) * rd + bv.w;
        v0 = v0 > 0.f ? v0 : (__expf(v0) - 1.f);
        v1 = v1 > 0.f ? v1 : (__expf(v1) - 1.f);
        v2 = v2 > 0.f ? v2 : (__expf(v2) - 1.f);
        v3 = v3 > 0.f ? v3 : (__expf(v3) - 1.f);
        *(float4*)&out[base] = make_float4(v0, v1, v2, v3);
    }
}

// ---------------------------------------------------------------------------
static void run_layer(const float* x, const float4* Wf, const float* asrc,
                      const float* adst, const float* bias, float* out)
{
    k_gemm_attn<<<NNODE / 16, 128>>>(x, Wf, asrc, adst);
    k_row_agg<<<T_TRIG * NHEADS * 2, 128>>>();
    k_col_agg<<<S_SPAN, 384>>>(bias, out);
}

extern "C" void kernel_launch(void* const* d_in, const int* in_sizes, int n_in,
                              void* d_out, int out_size)
{
    const float* x0  = (const float*)d_in[0];
    const float* W1  = (const float*)d_in[1];
    const float* as1 = (const float*)d_in[2];
    const float* ad1 = (const float*)d_in[3];
    const float* b1  = (const float*)d_in[4];
    const float* W2  = (const float*)d_in[5];
    const float* as2 = (const float*)d_in[6];
    const float* ad2 = (const float*)d_in[7];
    const float* b2  = (const float*)d_in[8];

    float* x1 = nullptr;
    cudaGetSymbolAddress((void**)&x1, g_x1);
    float4* Wf = nullptr;
    cudaGetSymbolAddress((void**)&Wf, g_Wf);

    k_prep<<<64, 256>>>(W1, W2);
    run_layer(x0, Wf,        as1, ad1, b1, x1);
    run_layer(x1, Wf + 8192, as2, ad2, b2, (float*)d_out);
}